// round 6
// baseline (speedup 1.0000x reference)
#include <cuda_runtime.h>
#include <cuda_bf16.h>

// GraphConvDistanceLayer: out[i] = sum_{e: rows[e]==i} Param_W[params[e]] * x[cols[e]]
//                                 + Param_b[b_params[i]]
//
// Inputs (metadata order):
//   d_in[0] = x        float32 [N]      N = 262144
//   d_in[1] = Param_W  float32 [1280]
//   d_in[2] = Param_b  float32 [16]
//   d_in[3] = w_rows   int32   [E]      E = 16777216
//   d_in[4] = w_cols   int32   [E]
//   d_in[5] = w_params int32   [E]
//   d_in[6] = b_params int32   [N]
// Output: float32 [N]
//
// R5 profile: LTS-bound (L2 87.8%, DRAM 19.8%, issue 10.9%). R6: raise MLP
// to 8 edges/thread to saturate LTS; vectorize bias init.

#define GCD_NPARAMS 1280

// ---------------------------------------------------------------------------
// Kernel 1: out = Param_b[b_params]  (d_out arrives poisoned). Vectorized.
// Param_b is 16 floats -> staged in registers-friendly smem.
// ---------------------------------------------------------------------------
__global__ __launch_bounds__(256)
void gcd_bias_init(float4* __restrict__ out,
                   const float* __restrict__ Pb,
                   const int4* __restrict__ bp,
                   int n4) {
    __shared__ float sPb[16];
    if (threadIdx.x < 16) sPb[threadIdx.x] = Pb[threadIdx.x];
    __syncthreads();

    int i = blockIdx.x * blockDim.x + threadIdx.x;
    if (i < n4) {
        int4 b = bp[i];
        float4 o;
        o.x = sPb[b.x];
        o.y = sPb[b.y];
        o.z = sPb[b.z];
        o.w = sPb[b.w];
        out[i] = o;
    }
}

// Scalar bias tail (N % 4 != 0) — defensive.
__global__ __launch_bounds__(128)
void gcd_bias_tail(float* __restrict__ out,
                   const float* __restrict__ Pb,
                   const int* __restrict__ bp,
                   int start, int n) {
    int i = start + blockIdx.x * blockDim.x + threadIdx.x;
    if (i < n) out[i] = __ldg(&Pb[__ldg(&bp[i])]);
}

// ---------------------------------------------------------------------------
// Kernel 2: edge scatter, 8 edges/thread.
//  - 6 front-batched LDG.128 for the index streams (MLP_p1 = 6)
//  - 8 outstanding x-gathers (L2-resident, via __ldg)
//  - Param_W staged in smem (random LDS ~4 cyc vs divergent-LDG wavefronts)
//  - 8 atomicAdd -> REDG (no return trip), addresses uniform-spread
// ---------------------------------------------------------------------------
__global__ __launch_bounds__(256)
void gcd_edge_scatter8(const float* __restrict__ x,
                       const float* __restrict__ Pw,
                       const int4* __restrict__ rows,
                       const int4* __restrict__ cols,
                       const int4* __restrict__ params,
                       float* __restrict__ out,
                       int e8) {
    __shared__ float sPw[GCD_NPARAMS];
    for (int i = threadIdx.x; i < GCD_NPARAMS; i += blockDim.x)
        sPw[i] = Pw[i];
    __syncthreads();

    int i = blockIdx.x * blockDim.x + threadIdx.x;
    if (i >= e8) return;
    int j = i * 2;

    // Front-batch all index loads: 6 x LDG.128 in flight together.
    int4 c0 = cols[j];
    int4 c1 = cols[j + 1];
    int4 p0 = params[j];
    int4 p1 = params[j + 1];
    int4 r0 = rows[j];
    int4 r1 = rows[j + 1];

    // 8 independent x-gathers (L2 latency hidden by MLP=8).
    float xa = __ldg(&x[c0.x]);
    float xb = __ldg(&x[c0.y]);
    float xc = __ldg(&x[c0.z]);
    float xd = __ldg(&x[c0.w]);
    float xe = __ldg(&x[c1.x]);
    float xf = __ldg(&x[c1.y]);
    float xg = __ldg(&x[c1.z]);
    float xh = __ldg(&x[c1.w]);

    float v0 = sPw[p0.x] * xa;
    float v1 = sPw[p0.y] * xb;
    float v2 = sPw[p0.z] * xc;
    float v3 = sPw[p0.w] * xd;
    float v4 = sPw[p1.x] * xe;
    float v5 = sPw[p1.y] * xf;
    float v6 = sPw[p1.z] * xg;
    float v7 = sPw[p1.w] * xh;

    atomicAdd(&out[r0.x], v0);
    atomicAdd(&out[r0.y], v1);
    atomicAdd(&out[r0.z], v2);
    atomicAdd(&out[r0.w], v3);
    atomicAdd(&out[r1.x], v4);
    atomicAdd(&out[r1.y], v5);
    atomicAdd(&out[r1.z], v6);
    atomicAdd(&out[r1.w], v7);
}

// Scalar edge tail (E % 8 != 0) — defensive; E = 2^24 so normally unused.
__global__ __launch_bounds__(128)
void gcd_edge_tail(const float* __restrict__ x,
                   const float* __restrict__ Pw,
                   const int* __restrict__ rows,
                   const int* __restrict__ cols,
                   const int* __restrict__ params,
                   float* __restrict__ out,
                   int start, int E) {
    int e = start + blockIdx.x * blockDim.x + threadIdx.x;
    if (e < E) {
        float v = __ldg(&Pw[__ldg(&params[e])]) * __ldg(&x[__ldg(&cols[e])]);
        atomicAdd(&out[__ldg(&rows[e])], v);
    }
}

extern "C" void kernel_launch(void* const* d_in, const int* in_sizes, int n_in,
                              void* d_out, int out_size) {
    const float* x   = (const float*)d_in[0];
    const float* Pw  = (const float*)d_in[1];
    const float* Pb  = (const float*)d_in[2];
    const int* rows  = (const int*)d_in[3];
    const int* cols  = (const int*)d_in[4];
    const int* prm   = (const int*)d_in[5];
    const int* bp    = (const int*)d_in[6];
    float* out       = (float*)d_out;

    const int N = out_size;
    const int E = in_sizes[3];

    // 1) out = Param_b[b_params]  (also clears the 0xAA poison)
    const int n4 = N >> 2;
    if (n4 > 0) {
        gcd_bias_init<<<(n4 + 255) / 256, 256>>>(
            (float4*)out, Pb, (const int4*)bp, n4);
    }
    const int btail_start = n4 << 2;
    if (btail_start < N) {
        gcd_bias_tail<<<((N - btail_start) + 127) / 128, 128>>>(
            out, Pb, bp, btail_start, N);
    }

    // 2) scatter-accumulate the edges, 8 per thread
    const int e8 = E >> 3;
    if (e8 > 0) {
        gcd_edge_scatter8<<<(e8 + 255) / 256, 256>>>(
            x, Pw,
            (const int4*)rows, (const int4*)cols, (const int4*)prm,
            out, e8);
    }
    const int tail_start = e8 << 3;
    const int tail = E - tail_start;
    if (tail > 0) {
        gcd_edge_tail<<<(tail + 127) / 128, 128>>>(
            x, Pw, rows, cols, prm, out, tail_start, E);
    }
}

// round 12
// speedup vs baseline: 1.0153x; 1.0153x over previous
#include <cuda_runtime.h>
#include <cuda_bf16.h>

// GraphConvDistanceLayer: out[i] = sum_{e: rows[e]==i} Param_W[params[e]] * x[cols[e]]
//                                 + Param_b[b_params[i]]
//
// Inputs (metadata order):
//   d_in[0] = x        float32 [N]      N = 262144
//   d_in[1] = Param_W  float32 [1280]
//   d_in[2] = Param_b  float32 [16]
//   d_in[3] = w_rows   int32   [E]      E = 16777216
//   d_in[4] = w_cols   int32   [E]
//   d_in[5] = w_params int32   [E]
//   d_in[6] = b_params int32   [N]
// Output: float32 [N]
//
// Model (R5/R6 evidence): bound by per-SM LSU/L1tex divergent-lane op rate
// (E gather lanes + E atomic lanes) co-binding with LTS (~85-88%).
// Best measured shape: 4 edges/thread. R9 retry: same as R7 but WITHOUT the
// in-launch cudaFuncSetAttribute (only unproven API interaction with graph
// capture; removed to de-risk after container failure).

#define GCD_NPARAMS 1280

// ---------------------------------------------------------------------------
// Kernel 1: out = Param_b[b_params]  (d_out arrives poisoned). Vectorized.
// ---------------------------------------------------------------------------
__global__ __launch_bounds__(256)
void gcd_bias_init(float4* __restrict__ out,
                   const float* __restrict__ Pb,
                   const int4* __restrict__ bp,
                   int n4) {
    __shared__ float sPb[16];
    if (threadIdx.x < 16) sPb[threadIdx.x] = Pb[threadIdx.x];
    __syncthreads();

    int i = blockIdx.x * blockDim.x + threadIdx.x;
    if (i < n4) {
        int4 b = __ldcs(&bp[i]);   // streaming: read-once
        float4 o;
        o.x = sPb[b.x];
        o.y = sPb[b.y];
        o.z = sPb[b.z];
        o.w = sPb[b.w];
        out[i] = o;
    }
}

// Scalar bias tail (N % 4 != 0) — defensive.
__global__ __launch_bounds__(128)
void gcd_bias_tail(float* __restrict__ out,
                   const float* __restrict__ Pb,
                   const int* __restrict__ bp,
                   int start, int n) {
    int i = start + blockIdx.x * blockDim.x + threadIdx.x;
    if (i < n) out[i] = __ldg(&Pb[__ldg(&bp[i])]);
}

// ---------------------------------------------------------------------------
// Kernel 2: edge scatter, 4 edges/thread (measured-best shape).
//  - index streams via __ldcs (evict-first): don't pollute L1, keep x resident
//  - x gather via __ldg (L1-cached; hit rate capacity-capped ~22%)
//  - Param_W staged in smem (random LDS, cheapest divergent-read path)
//  - atomicAdd -> REDG (no return), uniform-spread addresses
// ---------------------------------------------------------------------------
__global__ __launch_bounds__(256)
void gcd_edge_scatter(const float* __restrict__ x,
                      const float* __restrict__ Pw,
                      const int4* __restrict__ rows,
                      const int4* __restrict__ cols,
                      const int4* __restrict__ params,
                      float* __restrict__ out,
                      int e4) {
    __shared__ float sPw[GCD_NPARAMS];
    for (int i = threadIdx.x; i < GCD_NPARAMS; i += blockDim.x)
        sPw[i] = Pw[i];
    __syncthreads();

    int i = blockIdx.x * blockDim.x + threadIdx.x;
    if (i >= e4) return;

    // Coalesced 16B streaming loads of 4 edges' indices.
    int4 c = __ldcs(&cols[i]);
    int4 p = __ldcs(&params[i]);
    int4 r = __ldcs(&rows[i]);

    // 4 independent x-gathers (L2/L1 latency overlapped).
    float xa = __ldg(&x[c.x]);
    float xb = __ldg(&x[c.y]);
    float xc = __ldg(&x[c.z]);
    float xd = __ldg(&x[c.w]);

    float v0 = sPw[p.x] * xa;
    float v1 = sPw[p.y] * xb;
    float v2 = sPw[p.z] * xc;
    float v3 = sPw[p.w] * xd;

    atomicAdd(&out[r.x], v0);
    atomicAdd(&out[r.y], v1);
    atomicAdd(&out[r.z], v2);
    atomicAdd(&out[r.w], v3);
}

// Scalar edge tail (E % 4 != 0) — defensive; E = 2^24 so normally unused.
__global__ __launch_bounds__(128)
void gcd_edge_tail(const float* __restrict__ x,
                   const float* __restrict__ Pw,
                   const int* __restrict__ rows,
                   const int* __restrict__ cols,
                   const int* __restrict__ params,
                   float* __restrict__ out,
                   int start, int E) {
    int e = start + blockIdx.x * blockDim.x + threadIdx.x;
    if (e < E) {
        float v = __ldg(&Pw[__ldg(&params[e])]) * __ldg(&x[__ldg(&cols[e])]);
        atomicAdd(&out[__ldg(&rows[e])], v);
    }
}

extern "C" void kernel_launch(void* const* d_in, const int* in_sizes, int n_in,
                              void* d_out, int out_size) {
    const float* x   = (const float*)d_in[0];
    const float* Pw  = (const float*)d_in[1];
    const float* Pb  = (const float*)d_in[2];
    const int* rows  = (const int*)d_in[3];
    const int* cols  = (const int*)d_in[4];
    const int* prm   = (const int*)d_in[5];
    const int* bp    = (const int*)d_in[6];
    float* out       = (float*)d_out;

    const int N = out_size;
    const int E = in_sizes[3];

    // 1) out = Param_b[b_params]  (also clears the 0xAA poison)
    const int n4 = N >> 2;
    if (n4 > 0) {
        gcd_bias_init<<<(n4 + 255) / 256, 256>>>(
            (float4*)out, Pb, (const int4*)bp, n4);
    }
    const int btail_start = n4 << 2;
    if (btail_start < N) {
        gcd_bias_tail<<<((N - btail_start) + 127) / 128, 128>>>(
            out, Pb, bp, btail_start, N);
    }

    // 2) scatter-accumulate the edges, 4 per thread
    const int e4 = E >> 2;
    if (e4 > 0) {
        gcd_edge_scatter<<<(e4 + 255) / 256, 256>>>(
            x, Pw,
            (const int4*)rows, (const int4*)cols, (const int4*)prm,
            out, e4);
    }
    const int tail_start = e4 << 2;
    const int tail = E - tail_start;
    if (tail > 0) {
        gcd_edge_tail<<<(tail + 127) / 128, 128>>>(
            x, Pw, rows, cols, prm, out, tail_start, E);
    }
}